// round 14
// baseline (speedup 1.0000x reference)
#include <cuda_runtime.h>
#include <math.h>

#define TOKENS     8192
#define MODEL_DIM  4096
#define PROMPT_DIM 64
#define NE         8
#define NP         4                          // expert pairs
#define TPW        4                          // tokens per warp
#define WARPS      16
#define TPB        (TPW * WARPS)              // 64 tokens per block
#define THREADS    512
#define GRID       (TOKENS / TPB)             // 128 CTAs, one wave
#define CHUNK      128                        // dims per K-chunk (float4 per lane, 512B burst)
#define NIT        (MODEL_DIM / CHUNK)        // 32
#define RING       3                          // prefetch distance 2

// d = a*b + d elementwise on packed fp32x2
__device__ __forceinline__ void ffma2(unsigned long long& d,
                                      unsigned long long a,
                                      unsigned long long b) {
    asm("fma.rn.f32x2 %0, %1, %2, %0;" : "+l"(d) : "l"(a), "l"(b));
}
__device__ __forceinline__ unsigned long long dup2(float v) {
    unsigned long long r;
    asm("mov.b64 %0, {%1, %1};" : "=l"(r) : "f"(v));
    return r;
}
__device__ __forceinline__ void unpack2(unsigned long long v, float& lo, float& hi) {
    asm("mov.b64 {%0, %1}, %2;" : "=f"(lo), "=f"(hi) : "l"(v));
}

__global__ __launch_bounds__(THREADS, 1)
void topkgate_kernel(const float* __restrict__ x,
                     const float* __restrict__ prompt,
                     const float* __restrict__ W,
                     const float* __restrict__ b,
                     float* __restrict__ out)
{
    const int tid   = threadIdx.x;
    const int w     = tid >> 5;
    const int lane  = tid & 31;
    const int tbase = blockIdx.x * TPB + w * TPW;   // grid covers TOKENS exactly

    // x base for this warp's 4 tokens (per-token offsets are immediates)
    const float* xb = x + (size_t)tbase * MODEL_DIM + 4 * lane;

    // ---- Ring prologue: start streaming x immediately (no W prologue at all) ----
    float4 buf[RING][TPW];
#pragma unroll
    for (int q = 0; q < RING - 1; q++)
#pragma unroll
        for (int m = 0; m < TPW; m++)
            buf[q][m] = __ldcs((const float4*)(xb + m * MODEL_DIM + q * CHUNK));

    // Packed accumulators: acc[m][p] = (logit[2p], logit[2p+1]) partial sums
    unsigned long long acc[TPW][NP];
#pragma unroll
    for (int m = 0; m < TPW; m++)
#pragma unroll
        for (int p = 0; p < NP; p++) acc[m][p] = 0ull;

    // W as u64 pairs: u64[d*4 + p] = (W[d][2p], W[d][2p+1])
    const ulonglong2* Wp = (const ulonglong2*)W;

    // ---- Mainloop: 3-deep register ring, distance 2; W straight from L1 ----
    for (int it = 0; it < NIT; it += RING) {
#pragma unroll
        for (int u = 0; u < RING; u++) {
            const int j = it + u;
            if (j < NIT) {
                // Prefetch chunk j+2 into ring slot (u+2)%3
                if (j + (RING - 1) < NIT) {
                    const int slot = (u + RING - 1) % RING;
#pragma unroll
                    for (int m = 0; m < TPW; m++)
                        buf[slot][m] = __ldcs(
                            (const float4*)(xb + m * MODEL_DIM + (j + RING - 1) * CHUNK));
                }

                // W rows d0..d0+3 (lane-contiguous 128 B): 8x LDG.128, L1-resident
                const int d0 = j * CHUNK + 4 * lane;
                const ulonglong2* wr = Wp + (size_t)d0 * 2;   // 2 ulonglong2 per row
                const ulonglong2 wa = __ldg(wr + 0), wb_ = __ldg(wr + 1);  // row d0
                const ulonglong2 wc = __ldg(wr + 2), wd = __ldg(wr + 3);   // row d0+1
                const ulonglong2 we = __ldg(wr + 4), wf = __ldg(wr + 5);   // row d0+2
                const ulonglong2 wg = __ldg(wr + 6), wh = __ldg(wr + 7);   // row d0+3

#pragma unroll
                for (int m = 0; m < TPW; m++) {
                    const float4 xv = buf[u][m];
                    const unsigned long long x0 = dup2(xv.x);
                    const unsigned long long x1 = dup2(xv.y);
                    const unsigned long long x2 = dup2(xv.z);
                    const unsigned long long x3 = dup2(xv.w);

                    ffma2(acc[m][0], x0, wa.x);  ffma2(acc[m][1], x0, wa.y);
                    ffma2(acc[m][2], x0, wb_.x); ffma2(acc[m][3], x0, wb_.y);
                    ffma2(acc[m][0], x1, wc.x);  ffma2(acc[m][1], x1, wc.y);
                    ffma2(acc[m][2], x1, wd.x);  ffma2(acc[m][3], x1, wd.y);
                    ffma2(acc[m][0], x2, we.x);  ffma2(acc[m][1], x2, we.y);
                    ffma2(acc[m][2], x2, wf.x);  ffma2(acc[m][3], x2, wf.y);
                    ffma2(acc[m][0], x3, wg.x);  ffma2(acc[m][1], x3, wg.y);
                    ffma2(acc[m][2], x3, wh.x);  ffma2(acc[m][3], x3, wh.y);
                }
            }
        }
    }

    // ---- Prompt tail: lane handles dims (4096 + 2*lane, +1) for all tokens ----
    {
        const int po = MODEL_DIM + 2 * lane;
        const ulonglong2* wr0 = Wp + (size_t)po * 2;        // row po: pairs 0-1, 2-3
        const ulonglong2 ta = __ldg(wr0 + 0), tb_ = __ldg(wr0 + 1);
        const ulonglong2 tc = __ldg(wr0 + 2), td = __ldg(wr0 + 3);  // row po+1
#pragma unroll
        for (int m = 0; m < TPW; m++) {
            const float2 pv = *(const float2*)(prompt + (size_t)(tbase + m) * PROMPT_DIM + 2 * lane);
            const unsigned long long plo = dup2(pv.x);
            const unsigned long long phi = dup2(pv.y);
            ffma2(acc[m][0], plo, ta.x);  ffma2(acc[m][1], plo, ta.y);
            ffma2(acc[m][2], plo, tb_.x); ffma2(acc[m][3], plo, tb_.y);
            ffma2(acc[m][0], phi, tc.x);  ffma2(acc[m][1], phi, tc.y);
            ffma2(acc[m][2], phi, td.x);  ffma2(acc[m][3], phi, td.y);
        }
    }

    // ---- Unpack to scalar accumulators ----
    float accf[TPW][NE];
#pragma unroll
    for (int m = 0; m < TPW; m++)
#pragma unroll
        for (int p = 0; p < NP; p++)
            unpack2(acc[m][p], accf[m][2 * p], accf[m][2 * p + 1]);

    // ---- Warp butterfly reduction over lanes ----
#pragma unroll
    for (int off = 16; off > 0; off >>= 1) {
#pragma unroll
        for (int m = 0; m < TPW; m++)
#pragma unroll
            for (int e = 0; e < NE; e++)
                accf[m][e] += __shfl_xor_sync(0xffffffffu, accf[m][e], off);
    }

    // ---- Epilogue: lane m handles token (tbase + m) ----
    if (lane < TPW) {
        const int t = tbase + lane;

        float lg[NE];
#pragma unroll
        for (int m = 0; m < TPW; m++) {
            if (lane == m) {
#pragma unroll
                for (int e = 0; e < NE; e++) lg[e] = accf[m][e];
            }
        }
#pragma unroll
        for (int e = 0; e < NE; e++) lg[e] += __ldg(b + e);

        // Top-2 with first-index tie-break (matches jax.lax.top_k)
        int i0 = 0; float m0 = lg[0];
#pragma unroll
        for (int e = 1; e < NE; e++)
            if (lg[e] > m0) { m0 = lg[e]; i0 = e; }
        int i1 = -1; float m1 = -INFINITY;
#pragma unroll
        for (int e = 0; e < NE; e++)
            if (e != i0 && lg[e] > m1) { m1 = lg[e]; i1 = e; }

        // Softmax over 8 (max-subtracted), gather top-2, renormalize with EPS clamp
        float s = 0.0f;
#pragma unroll
        for (int e = 0; e < NE; e++) s += __expf(lg[e] - m0);
        const float g0 = 1.0f / s;
        const float g1 = __expf(m1 - m0) / s;
        const float denom = fmaxf(g0 + g1, 1.1920929e-07f);
        const float r0 = g0 / denom;
        const float r1 = g1 / denom;

        // masks: [T, 2, 8] at offset 0
        float* mrow = out + (size_t)t * 16;
        const float4 z = make_float4(0.f, 0.f, 0.f, 0.f);
        *(float4*)(mrow + 0)  = z;
        *(float4*)(mrow + 4)  = z;
        *(float4*)(mrow + 8)  = z;
        *(float4*)(mrow + 12) = z;
        mrow[i0]     = 1.0f;
        mrow[8 + i1] = 1.0f;

        // gates_s: [T, 2] at offset T*16
        float* grow = out + (size_t)TOKENS * 16 + (size_t)t * 2;
        grow[0] = r0;
        grow[1] = r1;
    }
}

extern "C" void kernel_launch(void* const* d_in, const int* in_sizes, int n_in,
                              void* d_out, int out_size)
{
    const float* x      = (const float*)d_in[0];
    const float* prompt = (const float*)d_in[1];
    const float* W      = (const float*)d_in[2];
    const float* b      = (const float*)d_in[3];
    float* out          = (float*)d_out;

    topkgate_kernel<<<GRID, THREADS>>>(x, prompt, W, b, out);
}

// round 15
// speedup vs baseline: 2.5128x; 2.5128x over previous
#include <cuda_runtime.h>
#include <math.h>

#define TOKENS     8192
#define MODEL_DIM  4096
#define PROMPT_DIM 64
#define KTOT       (MODEL_DIM + PROMPT_DIM)   // 4160
#define NE         8
#define NP         4                          // expert pairs
#define TPW        4                          // tokens per warp
#define WARPS      16
#define TPB        (TPW * WARPS)              // 64 tokens per block
#define THREADS    512
#define GRID       (TOKENS / TPB)             // 128 CTAs, one wave
#define DSTRIDE    4162                       // per-pair row, float2 units
#define SMEM_BYTES (NP * DSTRIDE * 8)         // 133,184 B
#define CHUNK      256                        // dims per K-chunk (2x float4/lane = 1KB/token burst)
#define NIT        (MODEL_DIM / CHUNK)        // 16 (even)

// d = a*b + d elementwise on packed fp32x2
__device__ __forceinline__ void ffma2(unsigned long long& d,
                                      unsigned long long a,
                                      unsigned long long b) {
    asm("fma.rn.f32x2 %0, %1, %2, %0;" : "+l"(d) : "l"(a), "l"(b));
}
__device__ __forceinline__ unsigned long long dup2(float v) {
    unsigned long long r;
    asm("mov.b64 %0, {%1, %1};" : "=l"(r) : "f"(v));
    return r;
}
__device__ __forceinline__ void unpack2(unsigned long long v, float& lo, float& hi) {
    asm("mov.b64 {%0, %1}, %2;" : "=f"(lo), "=f"(hi) : "l"(v));
}

__global__ __launch_bounds__(THREADS, 1)
void topkgate_kernel(const float* __restrict__ x,
                     const float* __restrict__ prompt,
                     const float* __restrict__ W,
                     const float* __restrict__ b,
                     float* __restrict__ out)
{
    extern __shared__ float2 wsp[];   // wsp[p * DSTRIDE + d] = (W[d][2p], W[d][2p+1])

    const int tid   = threadIdx.x;
    const int w     = tid >> 5;
    const int lane  = tid & 31;
    const int tbase = blockIdx.x * TPB + w * TPW;   // grid covers TOKENS exactly

    // x base for this warp's 4 tokens; lane covers 128 dims/half via float4
    const float* xb = x + (size_t)tbase * MODEL_DIM + 4 * lane;

    // ---- Prologue: chunk 0 into buf A FIRST (latency overlaps W staging) ----
    // Per token: two back-to-back LDG.128 (1 KB contiguous per token).
    float4 bufA[TPW][2], bufB[TPW][2];
#pragma unroll
    for (int m = 0; m < TPW; m++) {
        bufA[m][0] = __ldcs((const float4*)(xb + m * MODEL_DIM));
        bufA[m][1] = __ldcs((const float4*)(xb + m * MODEL_DIM + 128));
    }

    // ---- Stage W into expert-paired SMEM layout ----
    {
        const float2* Wv = (const float2*)W;   // Wv[d*4 + p] = (W[d][2p], W[d][2p+1])
        for (int i = tid; i < KTOT * NP; i += THREADS) {
            int d = i >> 2;
            int p = i & 3;
            wsp[p * DSTRIDE + d] = Wv[i];
        }
    }
    __syncthreads();

    // Packed accumulators: acc[m][p] = (logit[2p], logit[2p+1]) partial sums
    unsigned long long acc[TPW][NP];
#pragma unroll
    for (int m = 0; m < TPW; m++)
#pragma unroll
        for (int p = 0; p < NP; p++) acc[m][p] = 0ull;

    // ---- Mainloop: double-buffered 256-dim chunks, distance-1 (long iters) ----
#define PREFETCH(DST, J)                                                        \
    if ((J) < NIT) {                                                            \
        _Pragma("unroll")                                                       \
        for (int m = 0; m < TPW; m++) {                                         \
            DST[m][0] = __ldcs((const float4*)(xb + m * MODEL_DIM + (J) * CHUNK));        \
            DST[m][1] = __ldcs((const float4*)(xb + m * MODEL_DIM + (J) * CHUNK + 128));  \
        }                                                                       \
    }

#define CONSUME(SRC, J)                                                         \
    {                                                                           \
        _Pragma("unroll")                                                       \
        for (int h = 0; h < 2; h++) {                                           \
            const int d0 = (J) * CHUNK + h * 128 + 4 * lane;                    \
            ulonglong2 wv0 = *(const ulonglong2*)&wsp[0 * DSTRIDE + d0];        \
            ulonglong2 wv0b = *(const ulonglong2*)&wsp[0 * DSTRIDE + d0 + 2];   \
            ulonglong2 wv1 = *(const ulonglong2*)&wsp[1 * DSTRIDE + d0];        \
            ulonglong2 wv1b = *(const ulonglong2*)&wsp[1 * DSTRIDE + d0 + 2];   \
            ulonglong2 wv2 = *(const ulonglong2*)&wsp[2 * DSTRIDE + d0];        \
            ulonglong2 wv2b = *(const ulonglong2*)&wsp[2 * DSTRIDE + d0 + 2];   \
            ulonglong2 wv3 = *(const ulonglong2*)&wsp[3 * DSTRIDE + d0];        \
            ulonglong2 wv3b = *(const ulonglong2*)&wsp[3 * DSTRIDE + d0 + 2];   \
            _Pragma("unroll")                                                   \
            for (int m = 0; m < TPW; m++) {                                     \
                const float4 xv = SRC[m][h];                                    \
                const unsigned long long x0 = dup2(xv.x);                       \
                const unsigned long long x1 = dup2(xv.y);                       \
                const unsigned long long x2 = dup2(xv.z);                       \
                const unsigned long long x3 = dup2(xv.w);                       \
                ffma2(acc[m][0], x0, wv0.x);  ffma2(acc[m][1], x0, wv1.x);      \
                ffma2(acc[m][2], x0, wv2.x);  ffma2(acc[m][3], x0, wv3.x);      \
                ffma2(acc[m][0], x1, wv0.y);  ffma2(acc[m][1], x1, wv1.y);      \
                ffma2(acc[m][2], x1, wv2.y);  ffma2(acc[m][3], x1, wv3.y);      \
                ffma2(acc[m][0], x2, wv0b.x); ffma2(acc[m][1], x2, wv1b.x);     \
                ffma2(acc[m][2], x2, wv2b.x); ffma2(acc[m][3], x2, wv3b.x);     \
                ffma2(acc[m][0], x3, wv0b.y); ffma2(acc[m][1], x3, wv1b.y);     \
                ffma2(acc[m][2], x3, wv2b.y); ffma2(acc[m][3], x3, wv3b.y);     \
            }                                                                   \
        }                                                                       \
    }

    for (int it = 0; it < NIT; it += 2) {
        PREFETCH(bufB, it + 1)
        CONSUME(bufA, it)
        PREFETCH(bufA, it + 2)
        CONSUME(bufB, it + 1)
    }
#undef PREFETCH
#undef CONSUME

    // ---- Prompt tail: lane handles dims (4096 + 2*lane, +1) for all tokens ----
    {
        const int po = MODEL_DIM + 2 * lane;
        ulonglong2 wp[NP];
#pragma unroll
        for (int p = 0; p < NP; p++)
            wp[p] = *(const ulonglong2*)&wsp[p * DSTRIDE + po];
#pragma unroll
        for (int m = 0; m < TPW; m++) {
            const float2 pv = *(const float2*)(prompt + (size_t)(tbase + m) * PROMPT_DIM + 2 * lane);
            const unsigned long long plo = dup2(pv.x);
            const unsigned long long phi = dup2(pv.y);
#pragma unroll
            for (int p = 0; p < NP; p++) {
                ffma2(acc[m][p], plo, wp[p].x);
                ffma2(acc[m][p], phi, wp[p].y);
            }
        }
    }

    // ---- Unpack to scalar accumulators ----
    float accf[TPW][NE];
#pragma unroll
    for (int m = 0; m < TPW; m++)
#pragma unroll
        for (int p = 0; p < NP; p++)
            unpack2(acc[m][p], accf[m][2 * p], accf[m][2 * p + 1]);

    // ---- Warp butterfly reduction over lanes ----
#pragma unroll
    for (int off = 16; off > 0; off >>= 1) {
#pragma unroll
        for (int m = 0; m < TPW; m++)
#pragma unroll
            for (int e = 0; e < NE; e++)
                accf[m][e] += __shfl_xor_sync(0xffffffffu, accf[m][e], off);
    }

    // ---- Epilogue: lane m handles token (tbase + m) ----
    if (lane < TPW) {
        const int t = tbase + lane;

        float lg[NE];
#pragma unroll
        for (int m = 0; m < TPW; m++) {
            if (lane == m) {
#pragma unroll
                for (int e = 0; e < NE; e++) lg[e] = accf[m][e];
            }
        }
#pragma unroll
        for (int e = 0; e < NE; e++) lg[e] += b[e];

        // Top-2 with first-index tie-break (matches jax.lax.top_k)
        int i0 = 0; float m0 = lg[0];
#pragma unroll
        for (int e = 1; e < NE; e++)
            if (lg[e] > m0) { m0 = lg[e]; i0 = e; }
        int i1 = -1; float m1 = -INFINITY;
#pragma unroll
        for (int e = 0; e < NE; e++)
            if (e != i0 && lg[e] > m1) { m1 = lg[e]; i1 = e; }

        // Softmax over 8 (max-subtracted), gather top-2, renormalize with EPS clamp
        float s = 0.0f;
#pragma unroll
        for (int e = 0; e < NE; e++) s += __expf(lg[e] - m0);
        const float g0 = 1.0f / s;
        const float g1 = __expf(m1 - m0) / s;
        const float denom = fmaxf(g0 + g1, 1.1920929e-07f);
        const float r0 = g0 / denom;
        const float r1 = g1 / denom;

        // masks: [T, 2, 8] at offset 0
        float* mrow = out + (size_t)t * 16;
        const float4 z = make_float4(0.f, 0.f, 0.f, 0.f);
        *(float4*)(mrow + 0)  = z;
        *(float4*)(mrow + 4)  = z;
        *(float4*)(mrow + 8)  = z;
        *(float4*)(mrow + 12) = z;
        mrow[i0]     = 1.0f;
        mrow[8 + i1] = 1.0f;

        // gates_s: [T, 2] at offset T*16
        float* grow = out + (size_t)TOKENS * 16 + (size_t)t * 2;
        grow[0] = r0;
        grow[1] = r1;
    }
}

extern "C" void kernel_launch(void* const* d_in, const int* in_sizes, int n_in,
                              void* d_out, int out_size)
{
    const float* x      = (const float*)d_in[0];
    const float* prompt = (const float*)d_in[1];
    const float* W      = (const float*)d_in[2];
    const float* b      = (const float*)d_in[3];
    float* out          = (float*)d_out;

    cudaFuncSetAttribute(topkgate_kernel,
                         cudaFuncAttributeMaxDynamicSharedMemorySize, SMEM_BYTES);

    topkgate_kernel<<<GRID, THREADS, SMEM_BYTES>>>(x, prompt, W, b, out);
}